// round 17
// baseline (speedup 1.0000x reference)
#include <cuda_runtime.h>
#include <cuda_fp16.h>
#include <cstdint>

#define N_NODES 100000
#define N_FEAT  128
#define N_EDGES 1600000
#define SCAN_CHUNK 1024
#define NBLK ((N_NODES + SCAN_CHUNK - 1) / SCAN_CHUNK)   // 98
#define APAD 72

// Scratch (__device__ globals: allocation-free).
__device__ int      g_degi[N_NODES];
__device__ int      g_rowstart[N_NODES];   // chunk-local exclusive prefix
__device__ int      g_cursor[N_NODES];     // zeroed by gather each launch
__device__ int      g_bsum[128];
__device__ int      g_boff[128];
__device__ int      g_scan_ctr;            // last-block ticket (self-resetting)
__device__ int      g_srcs[N_EDGES];
__device__ float    g_dinv[N_NODES];
__device__ uint32_t g_BfragH[8 * 16 * 32 * 2];       // fp16 W frags (half2 each)
__device__ __half   g_xwh[(size_t)N_NODES * N_FEAT]; // (x@W^T)*dinv[row], fp16

// ---------------------------------------------------------------------------
// 1) fused: zero degree counters + pack W into fp16 m16n8k16 B-fragments.
__global__ void k_init_bpack(const float* __restrict__ W) {
    const int t = blockIdx.x * blockDim.x + threadIdx.x;
    if (t < N_NODES) g_degi[t] = 0;
    if (t < 8 * 16 * 32) {
        const int lane = t & 31;
        const int nc   = (t >> 5) & 15;
        const int kc   = t >> 9;
        const int g  = lane >> 2;
        const int tg = lane & 3;
        const int k = kc * 16 + tg * 2;
        const int n = nc * 8 + g;
        const __half2 b0 = __floats2half2_rn(W[n * N_FEAT + k],     W[n * N_FEAT + k + 1]);
        const __half2 b1 = __floats2half2_rn(W[n * N_FEAT + k + 8], W[n * N_FEAT + k + 9]);
        const int base = ((kc * 2 + (nc >> 3)) * 32 + lane) * 16 + (nc & 7) * 2;
        g_BfragH[base + 0] = *reinterpret_cast<const uint32_t*>(&b0);
        g_BfragH[base + 1] = *reinterpret_cast<const uint32_t*>(&b1);
    }
}

// 2) degree count, 4 edges/thread
__global__ void k_deg_count(const int* __restrict__ col) {
    const int q = blockIdx.x * blockDim.x + threadIdx.x;
    if (q < N_EDGES / 4) {
        const int4 c4 = reinterpret_cast<const int4*>(col)[q];
        atomicAdd(&g_degi[c4.x], 1);
        atomicAdd(&g_degi[c4.y], 1);
        atomicAdd(&g_degi[c4.z], 1);
        atomicAdd(&g_degi[c4.w], 1);
    }
}

// 3) scan stage 1 (+ dinv) with last-block boff computation (replaces scan23).
__global__ void k_scan1() {
    __shared__ int sh[256];
    __shared__ int is_last;
    const int t = threadIdx.x;
    const int base = blockIdx.x * SCAN_CHUNK + t * 4;
    int v[4], s = 0;
    #pragma unroll
    for (int i = 0; i < 4; ++i) {
        int idx = base + i;
        v[i] = (idx < N_NODES) ? g_degi[idx] : 0;
        if (idx < N_NODES) g_dinv[idx] = rsqrtf((float)(v[i] + 1));
        s += v[i];
    }
    sh[t] = s; __syncthreads();
    #pragma unroll
    for (int off = 1; off < 256; off <<= 1) {
        int add = (t >= off) ? sh[t - off] : 0;
        __syncthreads();
        sh[t] += add;
        __syncthreads();
    }
    if (t == 255) g_bsum[blockIdx.x] = sh[255];
    int run = sh[t] - s;
    #pragma unroll
    for (int i = 0; i < 4; ++i) {
        int idx = base + i;
        if (idx < N_NODES) g_rowstart[idx] = run;
        run += v[i];
    }

    // Last block scans the 98 block sums into g_boff.
    __threadfence();
    __syncthreads();
    if (t == 0) is_last = (atomicAdd(&g_scan_ctr, 1) == NBLK - 1);
    __syncthreads();
    if (is_last) {
        int bv = 0;
        if (t < 128) { bv = (t < NBLK) ? g_bsum[t] : 0; sh[t] = bv; }
        __syncthreads();
        #pragma unroll
        for (int off = 1; off < 128; off <<= 1) {
            int add = 0;
            if (t < 128 && t >= off) add = sh[t - off];
            __syncthreads();
            if (t < 128) sh[t] += add;
            __syncthreads();
        }
        if (t < 128) g_boff[t] = sh[t] - bv;   // exclusive
        if (t == 0) g_scan_ctr = 0;            // restore for next launch
    }
}

// ---------------------------------------------------------------------------
#define MMA_F16(acc, a0, a1, a2, a3, b0, b1)                                   \
    asm volatile("mma.sync.aligned.m16n8k16.row.col.f32.f16.f16.f32 "          \
                 "{%0,%1,%2,%3}, {%4,%5,%6,%7}, {%8,%9}, {%0,%1,%2,%3};"       \
                 : "+f"(acc[0]), "+f"(acc[1]), "+f"(acc[2]), "+f"(acc[3])      \
                 : "r"(a0), "r"(a1), "r"(a2), "r"(a3), "r"(b0), "r"(b1))

// 4) GEMM (profiled): g_xwh = half((x @ W^T) * dinv[row]).
//    Single-term fp16; reg-capped to 64 for 4 blocks/SM.
__global__ __launch_bounds__(256, 4) void k_gemm(const float* __restrict__ x) {
    __shared__ uint32_t shi[64][APAD];                 // 18.4 KB
    const int t    = threadIdx.x;
    const int warp = t >> 5;
    const int lane = t & 31;
    const int row0  = blockIdx.x * 64;
    const int nrows = min(64, N_NODES - row0);

    const float4* src = reinterpret_cast<const float4*>(x + (size_t)row0 * N_FEAT);
    for (int idx = t; idx < nrows * 32; idx += 256) {
        const int r  = idx >> 5, c4 = idx & 31;
        const float4 v = src[idx];
        const __half2 h0 = __floats2half2_rn(v.x, v.y);
        const __half2 h1 = __floats2half2_rn(v.z, v.w);
        const int kc  = c4 >> 2;
        const int pp0 = (2 * c4) & 7, pp1 = pp0 + 1;
        const int o0  = kc * 8 + (pp0 & 3) * 2 + (pp0 >> 2);
        const int o1  = kc * 8 + (pp1 & 3) * 2 + (pp1 >> 2);
        shi[r][o0] = *reinterpret_cast<const uint32_t*>(&h0);
        shi[r][o1] = *reinterpret_cast<const uint32_t*>(&h1);
    }
    __syncthreads();

    const int g   = lane >> 2;
    const int tg  = lane & 3;
    const int rb  = (warp & 3) * 16;
    const int h   = warp >> 2;
    const int nc0 = h * 8;

    float acc[8][4];
    #pragma unroll
    for (int j = 0; j < 8; ++j)
        acc[j][0] = acc[j][1] = acc[j][2] = acc[j][3] = 0.f;

    const uint4* bp = reinterpret_cast<const uint4*>(g_BfragH)
                      + ((size_t)h * 32 + lane) * 4;

    uint4 bcur[4];
    #pragma unroll
    for (int j = 0; j < 4; ++j) bcur[j] = bp[j];

    #pragma unroll
    for (int kc = 0; kc < 8; ++kc) {
        const uint2 ahr0 = *reinterpret_cast<const uint2*>(&shi[rb + g][kc * 8 + tg * 2]);
        const uint2 ahr1 = *reinterpret_cast<const uint2*>(&shi[rb + g + 8][kc * 8 + tg * 2]);

        uint4 bnxt[4];
        if (kc < 7) {
            #pragma unroll
            for (int j = 0; j < 4; ++j) bnxt[j] = bp[(kc + 1) * 256 + j];
        }

        #pragma unroll
        for (int j = 0; j < 4; ++j) {
            MMA_F16(acc[2*j],     ahr0.x, ahr1.x, ahr0.y, ahr1.y, bcur[j].x, bcur[j].y);
            MMA_F16(acc[2*j + 1], ahr0.x, ahr1.x, ahr0.y, ahr1.y, bcur[j].z, bcur[j].w);
        }
        if (kc < 7) {
            #pragma unroll
            for (int j = 0; j < 4; ++j) bcur[j] = bnxt[j];
        }
    }

    const int r0 = row0 + rb + g;
    const int r1 = r0 + 8;
    const float d0 = (r0 < N_NODES) ? g_dinv[r0] : 0.f;
    const float d1 = (r1 < N_NODES) ? g_dinv[r1] : 0.f;
    #pragma unroll
    for (int j = 0; j < 8; ++j) {
        const int col = (nc0 + j) * 8 + tg * 2;
        if (r0 < N_NODES)
            *reinterpret_cast<__half2*>(&g_xwh[(size_t)r0 * N_FEAT + col]) =
                __floats2half2_rn(acc[j][0] * d0, acc[j][1] * d0);
        if (r1 < N_NODES)
            *reinterpret_cast<__half2*>(&g_xwh[(size_t)r1 * N_FEAT + col]) =
                __floats2half2_rn(acc[j][2] * d1, acc[j][3] * d1);
    }
}

// 5) bucket-fill, 4 edges/thread; applies boff inline (cursor starts at 0).
__global__ void k_fill(const int* __restrict__ ei) {
    const int q = blockIdx.x * blockDim.x + threadIdx.x;
    if (q < N_EDGES / 4) {
        const int4 s4 = reinterpret_cast<const int4*>(ei)[q];
        const int4 c4 = reinterpret_cast<const int4*>(ei + N_EDGES)[q];
        g_srcs[g_rowstart[c4.x] + g_boff[c4.x >> 10] + atomicAdd(&g_cursor[c4.x], 1)] = s4.x;
        g_srcs[g_rowstart[c4.y] + g_boff[c4.y >> 10] + atomicAdd(&g_cursor[c4.y], 1)] = s4.y;
        g_srcs[g_rowstart[c4.z] + g_boff[c4.z >> 10] + atomicAdd(&g_cursor[c4.z], 1)] = s4.z;
        g_srcs[g_rowstart[c4.w] + g_boff[c4.w >> 10] + atomicAdd(&g_cursor[c4.w], 1)] = s4.w;
    }
}

// ---------------------------------------------------------------------------
// 6) Pull aggregation: one warp per target; fp16 rows, fp32 accumulation.
//    Also restores g_cursor[c] = 0 for the next launch (replay invariant).
__global__ __launch_bounds__(256) void k_gather(const float* __restrict__ b,
                                                float* __restrict__ out) {
    const int warp = (blockIdx.x * blockDim.x + threadIdx.x) >> 5;
    const int lane = threadIdx.x & 31;
    if (warp >= N_NODES) return;
    const int c = warp;

    const int base = g_rowstart[c] + g_boff[c >> 10];
    const int cnt  = g_degi[c];
    if (lane == 0) g_cursor[c] = 0;          // restore invariant

    float4 a0 = make_float4(0.f,0.f,0.f,0.f), a1 = a0, a2 = a0, a3 = a0;
    const uint2* xw = reinterpret_cast<const uint2*>(g_xwh);   // 8B = 4 halves

    int i = 0;
    for (; i + 4 <= cnt; i += 4) {
        const int s0 = g_srcs[base + i + 0];
        const int s1 = g_srcs[base + i + 1];
        const int s2 = g_srcs[base + i + 2];
        const int s3 = g_srcs[base + i + 3];
        const uint2 v0 = xw[(size_t)s0 * 32 + lane];
        const uint2 v1 = xw[(size_t)s1 * 32 + lane];
        const uint2 v2 = xw[(size_t)s2 * 32 + lane];
        const uint2 v3 = xw[(size_t)s3 * 32 + lane];
        {
            const float2 p = __half22float2(*(const __half2*)&v0.x);
            const float2 q = __half22float2(*(const __half2*)&v0.y);
            a0.x += p.x; a0.y += p.y; a0.z += q.x; a0.w += q.y;
        }
        {
            const float2 p = __half22float2(*(const __half2*)&v1.x);
            const float2 q = __half22float2(*(const __half2*)&v1.y);
            a1.x += p.x; a1.y += p.y; a1.z += q.x; a1.w += q.y;
        }
        {
            const float2 p = __half22float2(*(const __half2*)&v2.x);
            const float2 q = __half22float2(*(const __half2*)&v2.y);
            a2.x += p.x; a2.y += p.y; a2.z += q.x; a2.w += q.y;
        }
        {
            const float2 p = __half22float2(*(const __half2*)&v3.x);
            const float2 q = __half22float2(*(const __half2*)&v3.y);
            a3.x += p.x; a3.y += p.y; a3.z += q.x; a3.w += q.y;
        }
    }
    for (; i < cnt; ++i) {
        const int s = g_srcs[base + i];
        const uint2 v = xw[(size_t)s * 32 + lane];
        const float2 p = __half22float2(*(const __half2*)&v.x);
        const float2 q = __half22float2(*(const __half2*)&v.y);
        a0.x += p.x; a0.y += p.y; a0.z += q.x; a0.w += q.y;
    }

    const uint2 vs = xw[(size_t)c * 32 + lane];
    const float2 sp = __half22float2(*(const __half2*)&vs.x);
    const float2 sq = __half22float2(*(const __half2*)&vs.y);
    float4 acc = make_float4(a0.x + a1.x + a2.x + a3.x + sp.x,
                             a0.y + a1.y + a2.y + a3.y + sp.y,
                             a0.z + a1.z + a2.z + a3.z + sq.x,
                             a0.w + a1.w + a2.w + a3.w + sq.y);
    const float nc = g_dinv[c];
    const float4 bv = reinterpret_cast<const float4*>(b)[lane];
    reinterpret_cast<float4*>(out + (size_t)c * N_FEAT)[lane] =
        make_float4(acc.x * nc + bv.x, acc.y * nc + bv.y,
                    acc.z * nc + bv.z, acc.w * nc + bv.w);
}

// ---------------------------------------------------------------------------
extern "C" void kernel_launch(void* const* d_in, const int* in_sizes, int n_in,
                              void* d_out, int out_size) {
    const float* x  = (const float*)d_in[0];
    const int*   ei = (const int*)  d_in[1];
    const float* W  = (const float*)d_in[2];
    const float* b  = (const float*)d_in[3];
    float* out = (float*)d_out;

    k_init_bpack<<<(N_NODES + 255) / 256, 256>>>(W);               // 1
    k_deg_count <<<(N_EDGES / 4 + 255) / 256, 256>>>(ei + N_EDGES);// 2
    k_scan1     <<<NBLK, 256>>>();                                 // 3 (dinv+boff)
    k_gemm      <<<(N_NODES + 63) / 64, 256>>>(x);                 // 4 (profiled)
    k_fill      <<<(N_EDGES / 4 + 255) / 256, 256>>>(ei);          // 5
    k_gather    <<<(N_NODES * 32 + 255) / 256, 256>>>(b, out);     // 6
}